// round 15
// baseline (speedup 1.0000x reference)
#include <cuda_runtime.h>
#include <cuda_fp16.h>
#include <cstdint>

// ---------------------------------------------------------------- constants
#define N_TOKENS  65536
#define IN_DIM    2048
#define N_EXPERTS 64
#define TILE_M    256
#define BK        32
#define NITER     (IN_DIM / BK)       // 64
#define GROUP     4                   // chunks per B group
#define NGROUPS   (NITER / GROUP)     // 16
#define NTHREADS  256
#define GRID_CTAS (N_TOKENS / TILE_M) // 256

// ---------------- smem map (bytes) ----------------
// A staging: warp-private 2-stage ring; stage = {h1 256x80 | S 256x80}
#define A_OFF_S    20480
#define A_STAGE_B  40960
// B: 2 buffers x 4 chunks x (w1 64x80 | T 64x80)
#define B_BASE     81920
#define B_CHUNK_B  10240
#define B_OFF_T    5120
#define B_BUF_B    (GROUP * B_CHUNK_B)          // 40960
#define SMEM_BYTES (B_BASE + 2 * B_BUF_B)       // 163840 -> 1 CTA/SM

// scaled-sum split: S = fp16(h1 + BETA*(x - h1)), T = fp16(w1 + BETA*(w - w1))
// logit = main + (ST - main)/BETA   (verified R13/R14: rel_err 6.3e-6)
#define BETA      128.0f
#define INV_BETA  (1.0f / 128.0f)

// W pack: [chunk j=0..63][{w1,T}][n=0..63][k=0..31] fp16 (512 KB)
__device__ __align__(16) __half Wpack_g[NITER * 2 * N_EXPERTS * BK];

// ---------------------------------------------------------------- helpers
__device__ __forceinline__ uint32_t smem_u32(const void* p) {
    uint32_t a;
    asm("{ .reg .u64 t; cvta.to.shared.u64 t, %1; cvt.u32.u64 %0, t; }" : "=r"(a) : "l"(p));
    return a;
}

__device__ __forceinline__ void ldsm4(uint32_t* r, uint32_t addr) {
    asm volatile("ldmatrix.sync.aligned.m8n8.x4.shared.b16 {%0,%1,%2,%3}, [%4];"
                 : "=r"(r[0]), "=r"(r[1]), "=r"(r[2]), "=r"(r[3]) : "r"(addr));
}

__device__ __forceinline__ void mma_f32(float* c, const uint32_t* a,
                                        uint32_t b0, uint32_t b1) {
    asm volatile(
        "mma.sync.aligned.m16n8k16.row.col.f32.f16.f16.f32 "
        "{%0,%1,%2,%3}, {%4,%5,%6,%7}, {%8,%9}, {%0,%1,%2,%3};"
        : "+f"(c[0]), "+f"(c[1]), "+f"(c[2]), "+f"(c[3])
        : "r"(a[0]), "r"(a[1]), "r"(a[2]), "r"(a[3]), "r"(b0), "r"(b1));
}

__device__ __forceinline__ void cp_async16(uint32_t dst, const void* src) {
    asm volatile("cp.async.ca.shared.global [%0], [%1], 16;" :: "r"(dst), "l"(src));
}
#define CP_COMMIT() asm volatile("cp.async.commit_group;" ::: "memory")
#define CP_WAIT0()  asm volatile("cp.async.wait_group 0;" ::: "memory")

// ---------------------------------------------------------------- W split pre-kernel
__global__ void wsplit_kernel(const float* __restrict__ W) {
    int idx = blockIdx.x * 256 + threadIdx.x;   // e*2048 + k
    int e = idx >> 11;
    int k = idx & 2047;
    float w = W[idx];
    __half h1 = __float2half_rn(w);
    float  w1 = __half2float(h1);
    __half t  = __float2half_rn(fmaf(BETA, w - w1, w1));   // T = w1 + beta*(w-w1)
    int j = k >> 5, kk = k & 31;
    Wpack_g[(size_t)j * 4096 + 0 * 2048 + e * 32 + kk] = h1;
    Wpack_g[(size_t)j * 4096 + 1 * 2048 + e * 32 + kk] = t;
}

// ---------------------------------------------------------------- x conversion
// h1 = fp16(x); S = fp16(h1 + BETA*(x - h1))
__device__ __forceinline__ void cvt_store(char* Ab, uint32_t off, float4 v) {
    __half2 h1a = __floats2half2_rn(v.x, v.y);
    __half2 h1b = __floats2half2_rn(v.z, v.w);
    float2 fa = __half22float2(h1a);
    float2 fb = __half22float2(h1b);
    __half2 sa = __floats2half2_rn(fmaf(BETA, v.x - fa.x, fa.x),
                                   fmaf(BETA, v.y - fa.y, fa.y));
    __half2 sb = __floats2half2_rn(fmaf(BETA, v.z - fb.x, fb.x),
                                   fmaf(BETA, v.w - fb.y, fb.y));
    uint2 hh, ss;
    hh.x = *(uint32_t*)&h1a; hh.y = *(uint32_t*)&h1b;
    ss.x = *(uint32_t*)&sa;  ss.y = *(uint32_t*)&sb;
    *(uint2*)(Ab + off)           = hh;
    *(uint2*)(Ab + A_OFF_S + off) = ss;
}

// ---------------------------------------------------------------- main kernel
extern __shared__ __align__(16) char smch[];

__global__ void __launch_bounds__(NTHREADS, 1)
router_mma_kernel(const float* __restrict__ x, float* __restrict__ out) {
    const int tid  = threadIdx.x;
    const int w    = tid >> 5;
    const int lane = tid & 31;
    const int tokenBase = blockIdx.x * TILE_M;
    const uint32_t sb = smem_u32(smch);

    // ---- x LDG map: instr i covers rows w*32+i*4+(l>>3), float4 (l&7)
    const float* xbase = x + (size_t)(tokenBase + w * 32 + (lane >> 3)) * IN_DIM
                           + (lane & 7) * 4;
    const uint32_t st_base = (uint32_t)((w * 32 + (lane >> 3)) * 80 + (lane & 7) * 8);

    // ---- ldmatrix offsets; warp owns rows [w*32, w*32+32) -> 2 m-tiles
    const uint32_t a_ld = (uint32_t)((w * 32 + (lane & 15)) * 80 + ((lane >> 4) & 1) * 16);
    const uint32_t b_ld = (uint32_t)(((lane & 7) + ((lane >> 4) & 1) * 8) * 80
                                     + ((lane >> 3) & 1) * 16);

    float accM[2][32];   // fp32: main = h1*w1   (2 m-tiles x 8 n8 x 4 regs)
    float accS[2][32];   // fp32: ST   = S*T
    #pragma unroll
    for (int m = 0; m < 2; m++)
        #pragma unroll
        for (int i = 0; i < 32; i++) { accM[m][i] = 0.0f; accS[m][i] = 0.0f; }

    float4 xr[8];

    // ================= prologue =================
    {
        #pragma unroll
        for (int i = 0; i < 8; i++) {
            int gs    = tid + 256 * i;
            int c     = gs >> 9;
            int split = (gs >> 8) & 1;
            int seg   = gs & 255;
            uint32_t dst = B_BASE + (uint32_t)c * B_CHUNK_B + (uint32_t)split * B_OFF_T
                         + (uint32_t)(seg >> 2) * 80 + (uint32_t)(seg & 3) * 16;
            const char* src = (const char*)Wpack_g + (size_t)c * 8192
                            + (size_t)split * 4096 + (size_t)seg * 16;
            cp_async16(sb + dst, src);
        }
        CP_COMMIT();
        #pragma unroll
        for (int i = 0; i < 8; i++)
            xr[i] = *(const float4*)(xbase + (size_t)i * 4 * IN_DIM);
        #pragma unroll
        for (int i = 0; i < 8; i++)
            cvt_store(smch, st_base + (uint32_t)i * 320, xr[i]);
        CP_WAIT0();
        __syncthreads();
    }

    // ================= main loop: 16 groups x 4 chunks =================
    for (int g = 0; g < NGROUPS; g++) {
        if (g + 1 < NGROUPS) {
            const uint32_t nbuf = B_BASE + (uint32_t)((g + 1) & 1) * B_BUF_B;
            const char* gsrc = (const char*)Wpack_g + (size_t)(g + 1) * GROUP * 8192;
            #pragma unroll
            for (int i = 0; i < 8; i++) {
                int gs    = tid + 256 * i;
                int c     = gs >> 9;
                int split = (gs >> 8) & 1;
                int seg   = gs & 255;
                uint32_t dst = nbuf + (uint32_t)c * B_CHUNK_B + (uint32_t)split * B_OFF_T
                             + (uint32_t)(seg >> 2) * 80 + (uint32_t)(seg & 3) * 16;
                cp_async16(sb + dst, gsrc + (size_t)c * 8192 + (size_t)split * 4096
                                          + (size_t)seg * 16);
            }
            CP_COMMIT();
        }

        const uint32_t bbuf = B_BASE + (uint32_t)(g & 1) * B_BUF_B;

        #pragma unroll
        for (int c = 0; c < GROUP; c++) {
            const int jj = g * GROUP + c;
            const uint32_t astage = (uint32_t)(jj & 1) * A_STAGE_B;
            const uint32_t bchunk = bbuf + (uint32_t)c * B_CHUNK_B;

            // prefetch next x chunk (warp-private rows)
            if (jj + 1 < NITER) {
                #pragma unroll
                for (int i = 0; i < 8; i++)
                    xr[i] = *(const float4*)(xbase + (size_t)i * 4 * IN_DIM
                                                   + (size_t)(jj + 1) * BK);
            }

            // ---- compute chunk jj: 4 MMA phases, frag loads pipelined one
            //      phase ahead (each ldsm hidden behind a full 16-MMA phase) ----
            // P0=(main,k0) P1=(ST,k0) P2=(main,k1) P3=(ST,k1); buffers fA/fB.
            uint32_t fAw[4][4], fAa[2][4];   // even phases (main/k0, main/k1)
            uint32_t fBw[4][4], fBa[2][4];   // odd phases  (ST/k0,  ST/k1)

            // loads P0
            #pragma unroll
            for (int gg = 0; gg < 4; gg++)
                ldsm4(fAw[gg], sb + bchunk + b_ld + (uint32_t)gg * 1280);
            ldsm4(fAa[0], sb + astage + a_ld);
            ldsm4(fAa[1], sb + astage + a_ld + 1280);
            // loads P1
            #pragma unroll
            for (int gg = 0; gg < 4; gg++)
                ldsm4(fBw[gg], sb + bchunk + B_OFF_T + b_ld + (uint32_t)gg * 1280);
            ldsm4(fBa[0], sb + astage + A_OFF_S + a_ld);
            ldsm4(fBa[1], sb + astage + A_OFF_S + a_ld + 1280);

            // MMA P0 -> accM
            #pragma unroll
            for (int gg = 0; gg < 4; gg++)
                #pragma unroll
                for (int m = 0; m < 2; m++) {
                    mma_f32(&accM[m][(2 * gg) * 4],     fAa[m], fAw[gg][0], fAw[gg][1]);
                    mma_f32(&accM[m][(2 * gg + 1) * 4], fAa[m], fAw[gg][2], fAw[gg][3]);
                }

            // loads P2 (main, k1) into fA
            #pragma unroll
            for (int gg = 0; gg < 4; gg++)
                ldsm4(fAw[gg], sb + bchunk + b_ld + (uint32_t)gg * 1280 + 32);
            ldsm4(fAa[0], sb + astage + a_ld + 32);
            ldsm4(fAa[1], sb + astage + a_ld + 1280 + 32);

            // MMA P1 -> accS
            #pragma unroll
            for (int gg = 0; gg < 4; gg++)
                #pragma unroll
                for (int m = 0; m < 2; m++) {
                    mma_f32(&accS[m][(2 * gg) * 4],     fBa[m], fBw[gg][0], fBw[gg][1]);
                    mma_f32(&accS[m][(2 * gg + 1) * 4], fBa[m], fBw[gg][2], fBw[gg][3]);
                }

            // loads P3 (ST, k1) into fB
            #pragma unroll
            for (int gg = 0; gg < 4; gg++)
                ldsm4(fBw[gg], sb + bchunk + B_OFF_T + b_ld + (uint32_t)gg * 1280 + 32);
            ldsm4(fBa[0], sb + astage + A_OFF_S + a_ld + 32);
            ldsm4(fBa[1], sb + astage + A_OFF_S + a_ld + 1280 + 32);

            // MMA P2 -> accM
            #pragma unroll
            for (int gg = 0; gg < 4; gg++)
                #pragma unroll
                for (int m = 0; m < 2; m++) {
                    mma_f32(&accM[m][(2 * gg) * 4],     fAa[m], fAw[gg][0], fAw[gg][1]);
                    mma_f32(&accM[m][(2 * gg + 1) * 4], fAa[m], fAw[gg][2], fAw[gg][3]);
                }

            // MMA P3 -> accS
            #pragma unroll
            for (int gg = 0; gg < 4; gg++)
                #pragma unroll
                for (int m = 0; m < 2; m++) {
                    mma_f32(&accS[m][(2 * gg) * 4],     fBa[m], fBw[gg][0], fBw[gg][1]);
                    mma_f32(&accS[m][(2 * gg + 1) * 4], fBa[m], fBw[gg][2], fBw[gg][3]);
                }

            // stage next A chunk (warp-private -> __syncwarp only)
            if (jj + 1 < NITER) {
                char* Ab = smch + (size_t)((jj + 1) & 1) * A_STAGE_B;
                #pragma unroll
                for (int i = 0; i < 8; i++)
                    cvt_store(Ab, st_base + (uint32_t)i * 320, xr[i]);
            }
            __syncwarp();
        }

        CP_WAIT0();
        __syncthreads();
    }

    // ================= epilogue =================
    const int q  = lane >> 2;   // row-in-8
    const int qc = lane & 3;    // column quad slot
    float* outIdx = out;
    float* outW   = out + 2 * (size_t)N_TOKENS;
    float* probs  = out + 4 * (size_t)N_TOKENS;

    #pragma unroll
    for (int m = 0; m < 2; m++) {
        #pragma unroll
        for (int r = 0; r < 2; r++) {
            // logit = main + (ST - main)/BETA
            float v[16];
            #pragma unroll
            for (int f = 0; f < 8; f++) {
                float m0 = accM[m][f * 4 + 2 * r],     s0 = accS[m][f * 4 + 2 * r];
                float m1 = accM[m][f * 4 + 2 * r + 1], s1 = accS[m][f * 4 + 2 * r + 1];
                v[2 * f]     = fmaf(s0 - m0, INV_BETA, m0);
                v[2 * f + 1] = fmaf(s1 - m1, INV_BETA, m1);
            }
            // quad max
            float mx = v[0];
            #pragma unroll
            for (int i = 1; i < 16; i++) mx = fmaxf(mx, v[i]);
            mx = fmaxf(mx, __shfl_xor_sync(0xffffffffu, mx, 1));
            mx = fmaxf(mx, __shfl_xor_sync(0xffffffffu, mx, 2));

            // local top-2 on logits (e ascending within lane)
            float v1 = -3.4e38f, v2 = -3.4e38f;
            int   i1 = 0, i2 = 0;
            #pragma unroll
            for (int f = 0; f < 8; f++) {
                #pragma unroll
                for (int cch = 0; cch < 2; cch++) {
                    float val = v[2 * f + cch];
                    int   e   = f * 8 + qc * 2 + cch;
                    if (val > v1)      { v2 = v1; i2 = i1; v1 = val; i1 = e; }
                    else if (val > v2) { v2 = val; i2 = e; }
                }
            }
            // quad merge (tie -> lower index, matching jax)
            #pragma unroll
            for (int d = 1; d <= 2; d <<= 1) {
                float ov1 = __shfl_xor_sync(0xffffffffu, v1, d);
                int   oi1 = __shfl_xor_sync(0xffffffffu, i1, d);
                float ov2 = __shfl_xor_sync(0xffffffffu, v2, d);
                int   oi2 = __shfl_xor_sync(0xffffffffu, i2, d);
                bool bet1 = (ov1 > v1) || (ov1 == v1 && oi1 < i1);
                if (bet1) {
                    bool keepOld = (v1 > ov2) || (v1 == ov2 && i1 < oi2);
                    if (keepOld) { v2 = v1; i2 = i1; } else { v2 = ov2; i2 = oi2; }
                    v1 = ov1; i1 = oi1;
                } else {
                    bool bet2 = (ov1 > v2) || (ov1 == v2 && oi1 < i2);
                    if (bet2) { v2 = ov1; i2 = oi1; }
                }
            }

            // exp + quad sum
            float ssum = 0.0f;
            #pragma unroll
            for (int i = 0; i < 16; i++) { v[i] = __expf(v[i] - mx); ssum += v[i]; }
            ssum += __shfl_xor_sync(0xffffffffu, ssum, 1);
            ssum += __shfl_xor_sync(0xffffffffu, ssum, 2);
            float rinv = 1.0f / ssum;

            const int row = tokenBase + w * 32 + m * 16 + q + r * 8;
            float* pr = probs + (size_t)row * N_EXPERTS + qc * 2;
            #pragma unroll
            for (int f = 0; f < 8; f++) {
                float2 pv = make_float2(v[2 * f] * rinv, v[2 * f + 1] * rinv);
                *(float2*)(pr + f * 8) = pv;
            }
            if (qc == 0) {
                float p1 = __expf(v1 - mx), p2 = __expf(v2 - mx);
                outIdx[(size_t)row * 2 + 0] = (float)i1;
                outIdx[(size_t)row * 2 + 1] = (float)i2;
                float tw = 1.0f / (p1 + p2);
                outW[(size_t)row * 2 + 0] = p1 * tw;
                outW[(size_t)row * 2 + 1] = p2 * tw;
            }
        }
    }
}

// ---------------------------------------------------------------- launcher
extern "C" void kernel_launch(void* const* d_in, const int* in_sizes, int n_in,
                              void* d_out, int out_size) {
    const float* x = (const float*)d_in[0];   // [65536, 2048] fp32
    const float* W = (const float*)d_in[1];   // [64, 2048]   fp32
    float* out = (float*)d_out;

    static int configured = 0;
    if (!configured) {
        cudaFuncSetAttribute(router_mma_kernel,
                             cudaFuncAttributeMaxDynamicSharedMemorySize, SMEM_BYTES);
        configured = 1;
    }

    wsplit_kernel<<<(N_EXPERTS * IN_DIM) / 256, 256>>>(W);
    router_mma_kernel<<<GRID_CTAS, NTHREADS, SMEM_BYTES>>>(x, out);
}

// round 16
// speedup vs baseline: 1.0030x; 1.0030x over previous
#include <cuda_runtime.h>
#include <cuda_fp16.h>
#include <cstdint>

// ---------------------------------------------------------------- constants
#define N_TOKENS  65536
#define IN_DIM    2048
#define N_EXPERTS 64
#define TILE_M    256
#define BK        32
#define NITER     (IN_DIM / BK)       // 64
#define GROUP     4                   // chunks per B group
#define NGROUPS   (NITER / GROUP)     // 16
#define NTHREADS  256
#define GRID_CTAS (N_TOKENS / TILE_M) // 256

// ---------------- smem map (bytes) ----------------
// A staging: warp-private 2-stage ring; stage = {h1 256x80 | S 256x80}
#define A_OFF_S    20480
#define A_STAGE_B  40960
// B: 2 buffers x 4 chunks x (w1 64x80 | T 64x80)
#define B_BASE     81920
#define B_CHUNK_B  10240
#define B_OFF_T    5120
#define B_BUF_B    (GROUP * B_CHUNK_B)          // 40960
#define SMEM_BYTES (B_BASE + 2 * B_BUF_B)       // 163840 -> 1 CTA/SM

// scaled-sum split: S = fp16(h1 + BETA*(x - h1)), T = fp16(w1 + BETA*(w - w1))
// logit = main + (ST - main)/BETA   (verified R13/R14: rel_err 6.3e-6)
#define BETA      128.0f
#define INV_BETA  (1.0f / 128.0f)

// W pack: [chunk j=0..63][{w1,T}][n=0..63][k=0..31] fp16 (512 KB)
__device__ __align__(16) __half Wpack_g[NITER * 2 * N_EXPERTS * BK];

// ---------------------------------------------------------------- helpers
__device__ __forceinline__ uint32_t smem_u32(const void* p) {
    uint32_t a;
    asm("{ .reg .u64 t; cvta.to.shared.u64 t, %1; cvt.u32.u64 %0, t; }" : "=r"(a) : "l"(p));
    return a;
}

__device__ __forceinline__ void ldsm4(uint32_t* r, uint32_t addr) {
    asm volatile("ldmatrix.sync.aligned.m8n8.x4.shared.b16 {%0,%1,%2,%3}, [%4];"
                 : "=r"(r[0]), "=r"(r[1]), "=r"(r[2]), "=r"(r[3]) : "r"(addr));
}

__device__ __forceinline__ void mma_f32(float* c, const uint32_t* a,
                                        uint32_t b0, uint32_t b1) {
    asm volatile(
        "mma.sync.aligned.m16n8k16.row.col.f32.f16.f16.f32 "
        "{%0,%1,%2,%3}, {%4,%5,%6,%7}, {%8,%9}, {%0,%1,%2,%3};"
        : "+f"(c[0]), "+f"(c[1]), "+f"(c[2]), "+f"(c[3])
        : "r"(a[0]), "r"(a[1]), "r"(a[2]), "r"(a[3]), "r"(b0), "r"(b1));
}

__device__ __forceinline__ void cp_async16(uint32_t dst, const void* src) {
    asm volatile("cp.async.ca.shared.global [%0], [%1], 16;" :: "r"(dst), "l"(src));
}
#define CP_COMMIT() asm volatile("cp.async.commit_group;" ::: "memory")
#define CP_WAIT0()  asm volatile("cp.async.wait_group 0;" ::: "memory")

// ---------------------------------------------------------------- W split pre-kernel
__global__ void wsplit_kernel(const float* __restrict__ W) {
    int idx = blockIdx.x * 256 + threadIdx.x;   // e*2048 + k
    int e = idx >> 11;
    int k = idx & 2047;
    float w = W[idx];
    __half h1 = __float2half_rn(w);
    float  w1 = __half2float(h1);
    __half t  = __float2half_rn(fmaf(BETA, w - w1, w1));   // T = w1 + beta*(w-w1)
    int j = k >> 5, kk = k & 31;
    Wpack_g[(size_t)j * 4096 + 0 * 2048 + e * 32 + kk] = h1;
    Wpack_g[(size_t)j * 4096 + 1 * 2048 + e * 32 + kk] = t;
}

// ---------------------------------------------------------------- x conversion
// h1 = fp16(x); S = fp16(h1 + BETA*(x - h1))
__device__ __forceinline__ void cvt_store(char* Ab, uint32_t off, float4 v) {
    __half2 h1a = __floats2half2_rn(v.x, v.y);
    __half2 h1b = __floats2half2_rn(v.z, v.w);
    float2 fa = __half22float2(h1a);
    float2 fb = __half22float2(h1b);
    __half2 sa = __floats2half2_rn(fmaf(BETA, v.x - fa.x, fa.x),
                                   fmaf(BETA, v.y - fa.y, fa.y));
    __half2 sb = __floats2half2_rn(fmaf(BETA, v.z - fb.x, fb.x),
                                   fmaf(BETA, v.w - fb.y, fb.y));
    uint2 hh, ss;
    hh.x = *(uint32_t*)&h1a; hh.y = *(uint32_t*)&h1b;
    ss.x = *(uint32_t*)&sa;  ss.y = *(uint32_t*)&sb;
    *(uint2*)(Ab + off)           = hh;
    *(uint2*)(Ab + A_OFF_S + off) = ss;
}

// ---------------------------------------------------------------- main kernel
extern __shared__ __align__(16) char smch[];

__global__ void __launch_bounds__(NTHREADS, 1)
router_mma_kernel(const float* __restrict__ x, float* __restrict__ out) {
    const int tid  = threadIdx.x;
    const int w    = tid >> 5;
    const int lane = tid & 31;
    const int tokenBase = blockIdx.x * TILE_M;
    const uint32_t sb = smem_u32(smch);

    // ---- x LDG map: instr i covers rows w*32+i*4+(l>>3), float4 (l&7)
    const float* xbase = x + (size_t)(tokenBase + w * 32 + (lane >> 3)) * IN_DIM
                           + (lane & 7) * 4;
    const uint32_t st_base = (uint32_t)((w * 32 + (lane >> 3)) * 80 + (lane & 7) * 8);

    // ---- ldmatrix offsets; warp owns rows [w*32, w*32+32) -> 2 m-tiles
    const uint32_t a_ld = (uint32_t)((w * 32 + (lane & 15)) * 80 + ((lane >> 4) & 1) * 16);
    const uint32_t b_ld = (uint32_t)(((lane & 7) + ((lane >> 4) & 1) * 8) * 80
                                     + ((lane >> 3) & 1) * 16);

    float accM[2][32];   // fp32: main = h1*w1   (2 m-tiles x 8 n8 x 4 regs)
    float accS[2][32];   // fp32: ST   = S*T
    #pragma unroll
    for (int m = 0; m < 2; m++)
        #pragma unroll
        for (int i = 0; i < 32; i++) { accM[m][i] = 0.0f; accS[m][i] = 0.0f; }

    float4 xr[8];

    // ================= prologue =================
    {
        #pragma unroll
        for (int i = 0; i < 8; i++) {
            int gs    = tid + 256 * i;
            int c     = gs >> 9;
            int split = (gs >> 8) & 1;
            int seg   = gs & 255;
            uint32_t dst = B_BASE + (uint32_t)c * B_CHUNK_B + (uint32_t)split * B_OFF_T
                         + (uint32_t)(seg >> 2) * 80 + (uint32_t)(seg & 3) * 16;
            const char* src = (const char*)Wpack_g + (size_t)c * 8192
                            + (size_t)split * 4096 + (size_t)seg * 16;
            cp_async16(sb + dst, src);
        }
        CP_COMMIT();
        #pragma unroll
        for (int i = 0; i < 8; i++)
            xr[i] = *(const float4*)(xbase + (size_t)i * 4 * IN_DIM);
        #pragma unroll
        for (int i = 0; i < 8; i++)
            cvt_store(smch, st_base + (uint32_t)i * 320, xr[i]);
        CP_WAIT0();
        __syncthreads();
    }

    // ================= main loop: 16 groups x 4 chunks =================
    for (int g = 0; g < NGROUPS; g++) {
        if (g + 1 < NGROUPS) {
            const uint32_t nbuf = B_BASE + (uint32_t)((g + 1) & 1) * B_BUF_B;
            const char* gsrc = (const char*)Wpack_g + (size_t)(g + 1) * GROUP * 8192;
            #pragma unroll
            for (int i = 0; i < 8; i++) {
                int gs    = tid + 256 * i;
                int c     = gs >> 9;
                int split = (gs >> 8) & 1;
                int seg   = gs & 255;
                uint32_t dst = nbuf + (uint32_t)c * B_CHUNK_B + (uint32_t)split * B_OFF_T
                             + (uint32_t)(seg >> 2) * 80 + (uint32_t)(seg & 3) * 16;
                cp_async16(sb + dst, gsrc + (size_t)c * 8192 + (size_t)split * 4096
                                          + (size_t)seg * 16);
            }
            CP_COMMIT();
        }

        const uint32_t bbuf = B_BASE + (uint32_t)(g & 1) * B_BUF_B;

        #pragma unroll
        for (int c = 0; c < GROUP; c++) {
            const int jj = g * GROUP + c;
            const uint32_t astage = (uint32_t)(jj & 1) * A_STAGE_B;
            const uint32_t bchunk = bbuf + (uint32_t)c * B_CHUNK_B;

            // prefetch next x chunk (warp-private rows)
            if (jj + 1 < NITER) {
                #pragma unroll
                for (int i = 0; i < 8; i++)
                    xr[i] = *(const float4*)(xbase + (size_t)i * 4 * IN_DIM
                                                   + (size_t)(jj + 1) * BK);
            }

            // ---- compute chunk jj: 4 MMA phases, frag loads pipelined one
            //      phase ahead (each ldsm hidden behind a full 16-MMA phase) ----
            // P0=(main,k0) P1=(ST,k0) P2=(main,k1) P3=(ST,k1); buffers fA/fB.
            uint32_t fAw[4][4], fAa[2][4];   // even phases (main/k0, main/k1)
            uint32_t fBw[4][4], fBa[2][4];   // odd phases  (ST/k0,  ST/k1)

            // loads P0
            #pragma unroll
            for (int gg = 0; gg < 4; gg++)
                ldsm4(fAw[gg], sb + bchunk + b_ld + (uint32_t)gg * 1280);
            ldsm4(fAa[0], sb + astage + a_ld);
            ldsm4(fAa[1], sb + astage + a_ld + 1280);
            // loads P1
            #pragma unroll
            for (int gg = 0; gg < 4; gg++)
                ldsm4(fBw[gg], sb + bchunk + B_OFF_T + b_ld + (uint32_t)gg * 1280);
            ldsm4(fBa[0], sb + astage + A_OFF_S + a_ld);
            ldsm4(fBa[1], sb + astage + A_OFF_S + a_ld + 1280);

            // MMA P0 -> accM
            #pragma unroll
            for (int gg = 0; gg < 4; gg++)
                #pragma unroll
                for (int m = 0; m < 2; m++) {
                    mma_f32(&accM[m][(2 * gg) * 4],     fAa[m], fAw[gg][0], fAw[gg][1]);
                    mma_f32(&accM[m][(2 * gg + 1) * 4], fAa[m], fAw[gg][2], fAw[gg][3]);
                }

            // loads P2 (main, k1) into fA
            #pragma unroll
            for (int gg = 0; gg < 4; gg++)
                ldsm4(fAw[gg], sb + bchunk + b_ld + (uint32_t)gg * 1280 + 32);
            ldsm4(fAa[0], sb + astage + a_ld + 32);
            ldsm4(fAa[1], sb + astage + a_ld + 1280 + 32);

            // MMA P1 -> accS
            #pragma unroll
            for (int gg = 0; gg < 4; gg++)
                #pragma unroll
                for (int m = 0; m < 2; m++) {
                    mma_f32(&accS[m][(2 * gg) * 4],     fBa[m], fBw[gg][0], fBw[gg][1]);
                    mma_f32(&accS[m][(2 * gg + 1) * 4], fBa[m], fBw[gg][2], fBw[gg][3]);
                }

            // loads P3 (ST, k1) into fB
            #pragma unroll
            for (int gg = 0; gg < 4; gg++)
                ldsm4(fBw[gg], sb + bchunk + B_OFF_T + b_ld + (uint32_t)gg * 1280 + 32);
            ldsm4(fBa[0], sb + astage + A_OFF_S + a_ld + 32);
            ldsm4(fBa[1], sb + astage + A_OFF_S + a_ld + 1280 + 32);

            // MMA P2 -> accM
            #pragma unroll
            for (int gg = 0; gg < 4; gg++)
                #pragma unroll
                for (int m = 0; m < 2; m++) {
                    mma_f32(&accM[m][(2 * gg) * 4],     fAa[m], fAw[gg][0], fAw[gg][1]);
                    mma_f32(&accM[m][(2 * gg + 1) * 4], fAa[m], fAw[gg][2], fAw[gg][3]);
                }

            // MMA P3 -> accS
            #pragma unroll
            for (int gg = 0; gg < 4; gg++)
                #pragma unroll
                for (int m = 0; m < 2; m++) {
                    mma_f32(&accS[m][(2 * gg) * 4],     fBa[m], fBw[gg][0], fBw[gg][1]);
                    mma_f32(&accS[m][(2 * gg + 1) * 4], fBa[m], fBw[gg][2], fBw[gg][3]);
                }

            // stage next A chunk (warp-private -> __syncwarp only)
            if (jj + 1 < NITER) {
                char* Ab = smch + (size_t)((jj + 1) & 1) * A_STAGE_B;
                #pragma unroll
                for (int i = 0; i < 8; i++)
                    cvt_store(Ab, st_base + (uint32_t)i * 320, xr[i]);
            }
            __syncwarp();
        }

        CP_WAIT0();
        __syncthreads();
    }

    // ================= epilogue =================
    const int q  = lane >> 2;   // row-in-8
    const int qc = lane & 3;    // column quad slot
    float* outIdx = out;
    float* outW   = out + 2 * (size_t)N_TOKENS;
    float* probs  = out + 4 * (size_t)N_TOKENS;

    #pragma unroll
    for (int m = 0; m < 2; m++) {
        #pragma unroll
        for (int r = 0; r < 2; r++) {
            // logit = main + (ST - main)/BETA
            float v[16];
            #pragma unroll
            for (int f = 0; f < 8; f++) {
                float m0 = accM[m][f * 4 + 2 * r],     s0 = accS[m][f * 4 + 2 * r];
                float m1 = accM[m][f * 4 + 2 * r + 1], s1 = accS[m][f * 4 + 2 * r + 1];
                v[2 * f]     = fmaf(s0 - m0, INV_BETA, m0);
                v[2 * f + 1] = fmaf(s1 - m1, INV_BETA, m1);
            }
            // quad max
            float mx = v[0];
            #pragma unroll
            for (int i = 1; i < 16; i++) mx = fmaxf(mx, v[i]);
            mx = fmaxf(mx, __shfl_xor_sync(0xffffffffu, mx, 1));
            mx = fmaxf(mx, __shfl_xor_sync(0xffffffffu, mx, 2));

            // local top-2 on logits (e ascending within lane)
            float v1 = -3.4e38f, v2 = -3.4e38f;
            int   i1 = 0, i2 = 0;
            #pragma unroll
            for (int f = 0; f < 8; f++) {
                #pragma unroll
                for (int cch = 0; cch < 2; cch++) {
                    float val = v[2 * f + cch];
                    int   e   = f * 8 + qc * 2 + cch;
                    if (val > v1)      { v2 = v1; i2 = i1; v1 = val; i1 = e; }
                    else if (val > v2) { v2 = val; i2 = e; }
                }
            }
            // quad merge (tie -> lower index, matching jax)
            #pragma unroll
            for (int d = 1; d <= 2; d <<= 1) {
                float ov1 = __shfl_xor_sync(0xffffffffu, v1, d);
                int   oi1 = __shfl_xor_sync(0xffffffffu, i1, d);
                float ov2 = __shfl_xor_sync(0xffffffffu, v2, d);
                int   oi2 = __shfl_xor_sync(0xffffffffu, i2, d);
                bool bet1 = (ov1 > v1) || (ov1 == v1 && oi1 < i1);
                if (bet1) {
                    bool keepOld = (v1 > ov2) || (v1 == ov2 && i1 < oi2);
                    if (keepOld) { v2 = v1; i2 = i1; } else { v2 = ov2; i2 = oi2; }
                    v1 = ov1; i1 = oi1;
                } else {
                    bool bet2 = (ov1 > v2) || (ov1 == v2 && oi1 < i2);
                    if (bet2) { v2 = ov1; i2 = oi1; }
                }
            }

            // exp + quad sum
            float ssum = 0.0f;
            #pragma unroll
            for (int i = 0; i < 16; i++) { v[i] = __expf(v[i] - mx); ssum += v[i]; }
            ssum += __shfl_xor_sync(0xffffffffu, ssum, 1);
            ssum += __shfl_xor_sync(0xffffffffu, ssum, 2);
            float rinv = 1.0f / ssum;

            const int row = tokenBase + w * 32 + m * 16 + q + r * 8;
            float* pr = probs + (size_t)row * N_EXPERTS + qc * 2;
            #pragma unroll
            for (int f = 0; f < 8; f++) {
                float2 pv = make_float2(v[2 * f] * rinv, v[2 * f + 1] * rinv);
                *(float2*)(pr + f * 8) = pv;
            }
            if (qc == 0) {
                float p1 = __expf(v1 - mx), p2 = __expf(v2 - mx);
                outIdx[(size_t)row * 2 + 0] = (float)i1;
                outIdx[(size_t)row * 2 + 1] = (float)i2;
                float tw = 1.0f / (p1 + p2);
                outW[(size_t)row * 2 + 0] = p1 * tw;
                outW[(size_t)row * 2 + 1] = p2 * tw;
            }
        }
    }
}

// ---------------------------------------------------------------- launcher
extern "C" void kernel_launch(void* const* d_in, const int* in_sizes, int n_in,
                              void* d_out, int out_size) {
    const float* x = (const float*)d_in[0];   // [65536, 2048] fp32
    const float* W = (const float*)d_in[1];   // [64, 2048]   fp32
    float* out = (float*)d_out;

    static int configured = 0;
    if (!configured) {
        cudaFuncSetAttribute(router_mma_kernel,
                             cudaFuncAttributeMaxDynamicSharedMemorySize, SMEM_BYTES);
        configured = 1;
    }

    wsplit_kernel<<<(N_EXPERTS * IN_DIM) / 256, 256>>>(W);
    router_mma_kernel<<<GRID_CTAS, NTHREADS, SMEM_BYTES>>>(x, out);
}

// round 17
// speedup vs baseline: 1.0197x; 1.0166x over previous
#include <cuda_runtime.h>
#include <cuda_fp16.h>
#include <cstdint>

// ---------------------------------------------------------------- constants
#define N_TOKENS  65536
#define IN_DIM    2048
#define N_EXPERTS 64
#define TILE_M    256
#define BK        32
#define NITER     (IN_DIM / BK)       // 64
#define GROUP     4                   // chunks per B group
#define NGROUPS   (NITER / GROUP)     // 16
#define NTHREADS  256
#define GRID_CTAS (N_TOKENS / TILE_M) // 256

// ---------------- smem map (bytes) ----------------
// A staging: warp-private 2-stage ring; stage = {h1 256x80 | S 256x80}
#define A_OFF_S    20480
#define A_STAGE_B  40960
// B: 2 buffers x 4 chunks x (w1 64x80 | T 64x80)
#define B_BASE     81920
#define B_CHUNK_B  10240
#define B_OFF_T    5120
#define B_BUF_B    (GROUP * B_CHUNK_B)          // 40960
#define SMEM_BYTES (B_BASE + 2 * B_BUF_B)       // 163840 -> 1 CTA/SM

// scaled-sum split: S = fp16(h1 + BETA*(x - h1)), T = fp16(w1 + BETA*(w - w1))
// logit = main + (ST - main)/BETA   (verified R13/R14: rel_err 6.3e-6)
#define BETA      128.0f
#define INV_BETA  (1.0f / 128.0f)

// W pack: [chunk j=0..63][{w1,T}][n=0..63][k=0..31] fp16 (512 KB)
__device__ __align__(16) __half Wpack_g[NITER * 2 * N_EXPERTS * BK];

// ---------------------------------------------------------------- helpers
__device__ __forceinline__ uint32_t smem_u32(const void* p) {
    uint32_t a;
    asm("{ .reg .u64 t; cvta.to.shared.u64 t, %1; cvt.u32.u64 %0, t; }" : "=r"(a) : "l"(p));
    return a;
}

__device__ __forceinline__ void ldsm4(uint32_t* r, uint32_t addr) {
    asm volatile("ldmatrix.sync.aligned.m8n8.x4.shared.b16 {%0,%1,%2,%3}, [%4];"
                 : "=r"(r[0]), "=r"(r[1]), "=r"(r[2]), "=r"(r[3]) : "r"(addr));
}

__device__ __forceinline__ void mma_f32(float* c, const uint32_t* a,
                                        uint32_t b0, uint32_t b1) {
    asm volatile(
        "mma.sync.aligned.m16n8k16.row.col.f32.f16.f16.f32 "
        "{%0,%1,%2,%3}, {%4,%5,%6,%7}, {%8,%9}, {%0,%1,%2,%3};"
        : "+f"(c[0]), "+f"(c[1]), "+f"(c[2]), "+f"(c[3])
        : "r"(a[0]), "r"(a[1]), "r"(a[2]), "r"(a[3]), "r"(b0), "r"(b1));
}

__device__ __forceinline__ void cp_async16(uint32_t dst, const void* src) {
    asm volatile("cp.async.ca.shared.global [%0], [%1], 16;" :: "r"(dst), "l"(src));
}
#define CP_COMMIT() asm volatile("cp.async.commit_group;" ::: "memory")
#define CP_WAIT0()  asm volatile("cp.async.wait_group 0;" ::: "memory")

// ---------------------------------------------------------------- W split pre-kernel
__global__ void wsplit_kernel(const float* __restrict__ W) {
    int idx = blockIdx.x * 256 + threadIdx.x;   // e*2048 + k
    int e = idx >> 11;
    int k = idx & 2047;
    float w = W[idx];
    __half h1 = __float2half_rn(w);
    float  w1 = __half2float(h1);
    __half t  = __float2half_rn(fmaf(BETA, w - w1, w1));   // T = w1 + beta*(w-w1)
    int j = k >> 5, kk = k & 31;
    Wpack_g[(size_t)j * 4096 + 0 * 2048 + e * 32 + kk] = h1;
    Wpack_g[(size_t)j * 4096 + 1 * 2048 + e * 32 + kk] = t;
}

// ---------------------------------------------------------------- x conversion
// h1 = fp16(x); S = fp16(h1 + BETA*(x - h1))
__device__ __forceinline__ void cvt_store(char* Ab, uint32_t off, float4 v) {
    __half2 h1a = __floats2half2_rn(v.x, v.y);
    __half2 h1b = __floats2half2_rn(v.z, v.w);
    float2 fa = __half22float2(h1a);
    float2 fb = __half22float2(h1b);
    __half2 sa = __floats2half2_rn(fmaf(BETA, v.x - fa.x, fa.x),
                                   fmaf(BETA, v.y - fa.y, fa.y));
    __half2 sb = __floats2half2_rn(fmaf(BETA, v.z - fb.x, fb.x),
                                   fmaf(BETA, v.w - fb.y, fb.y));
    uint2 hh, ss;
    hh.x = *(uint32_t*)&h1a; hh.y = *(uint32_t*)&h1b;
    ss.x = *(uint32_t*)&sa;  ss.y = *(uint32_t*)&sb;
    *(uint2*)(Ab + off)           = hh;
    *(uint2*)(Ab + A_OFF_S + off) = ss;
}

// ---------------------------------------------------------------- main kernel
extern __shared__ __align__(16) char smch[];

__global__ void __launch_bounds__(NTHREADS, 1)
router_mma_kernel(const float* __restrict__ x, float* __restrict__ out) {
    const int tid  = threadIdx.x;
    const int w    = tid >> 5;
    const int lane = tid & 31;
    const int tokenBase = blockIdx.x * TILE_M;
    const uint32_t sb = smem_u32(smch);
    // SMSP pairing is (w, w+4): warps 4-7 run cvt-FIRST chunks so each SMSP
    // always has one warp in MMA phase while its partner is in ldsm/cvt phase.
    const bool cvtFirst = (w >= 4);

    // ---- x LDG map: instr i covers rows w*32+i*4+(l>>3), float4 (l&7)
    const float* xbase = x + (size_t)(tokenBase + w * 32 + (lane >> 3)) * IN_DIM
                           + (lane & 7) * 4;
    const uint32_t st_base = (uint32_t)((w * 32 + (lane >> 3)) * 80 + (lane & 7) * 8);

    // ---- ldmatrix offsets; warp owns rows [w*32, w*32+32) -> 2 m-tiles
    const uint32_t a_ld = (uint32_t)((w * 32 + (lane & 15)) * 80 + ((lane >> 4) & 1) * 16);
    const uint32_t b_ld = (uint32_t)(((lane & 7) + ((lane >> 4) & 1) * 8) * 80
                                     + ((lane >> 3) & 1) * 16);

    float accM[2][32];   // fp32: main = h1*w1   (2 m-tiles x 8 n8 x 4 regs)
    float accS[2][32];   // fp32: ST   = S*T
    #pragma unroll
    for (int m = 0; m < 2; m++)
        #pragma unroll
        for (int i = 0; i < 32; i++) { accM[m][i] = 0.0f; accS[m][i] = 0.0f; }

    float4 xr[8];

    // ================= prologue =================
    {
        #pragma unroll
        for (int i = 0; i < 8; i++) {
            int gs    = tid + 256 * i;
            int c     = gs >> 9;
            int split = (gs >> 8) & 1;
            int seg   = gs & 255;
            uint32_t dst = B_BASE + (uint32_t)c * B_CHUNK_B + (uint32_t)split * B_OFF_T
                         + (uint32_t)(seg >> 2) * 80 + (uint32_t)(seg & 3) * 16;
            const char* src = (const char*)Wpack_g + (size_t)c * 8192
                            + (size_t)split * 4096 + (size_t)seg * 16;
            cp_async16(sb + dst, src);
        }
        CP_COMMIT();
        #pragma unroll
        for (int i = 0; i < 8; i++)
            xr[i] = *(const float4*)(xbase + (size_t)i * 4 * IN_DIM);
        #pragma unroll
        for (int i = 0; i < 8; i++)
            cvt_store(smch, st_base + (uint32_t)i * 320, xr[i]);
        // cvt-first warps enter the loop holding chunk-1 data in xr
        if (cvtFirst) {
            #pragma unroll
            for (int i = 0; i < 8; i++)
                xr[i] = *(const float4*)(xbase + (size_t)i * 4 * IN_DIM + BK);
        }
        CP_WAIT0();
        __syncthreads();
    }

    // ================= main loop: 16 groups x 4 chunks =================
    for (int g = 0; g < NGROUPS; g++) {
        if (g + 1 < NGROUPS) {
            const uint32_t nbuf = B_BASE + (uint32_t)((g + 1) & 1) * B_BUF_B;
            const char* gsrc = (const char*)Wpack_g + (size_t)(g + 1) * GROUP * 8192;
            #pragma unroll
            for (int i = 0; i < 8; i++) {
                int gs    = tid + 256 * i;
                int c     = gs >> 9;
                int split = (gs >> 8) & 1;
                int seg   = gs & 255;
                uint32_t dst = nbuf + (uint32_t)c * B_CHUNK_B + (uint32_t)split * B_OFF_T
                             + (uint32_t)(seg >> 2) * 80 + (uint32_t)(seg & 3) * 16;
                cp_async16(sb + dst, gsrc + (size_t)c * 8192 + (size_t)split * 4096
                                          + (size_t)seg * 16);
            }
            CP_COMMIT();
        }

        const uint32_t bbuf = B_BASE + (uint32_t)(g & 1) * B_BUF_B;

        #pragma unroll
        for (int c = 0; c < GROUP; c++) {
            const int jj = g * GROUP + c;
            const uint32_t astage = (uint32_t)(jj & 1) * A_STAGE_B;
            const uint32_t bchunk = bbuf + (uint32_t)c * B_CHUNK_B;

            if (cvtFirst) {
                // cvt for chunk jj+1 first (xr holds jj+1 data), then prefetch jj+2
                if (jj + 1 < NITER) {
                    char* Ab = smch + (size_t)((jj + 1) & 1) * A_STAGE_B;
                    #pragma unroll
                    for (int i = 0; i < 8; i++)
                        cvt_store(Ab, st_base + (uint32_t)i * 320, xr[i]);
                }
                if (jj + 2 < NITER) {
                    #pragma unroll
                    for (int i = 0; i < 8; i++)
                        xr[i] = *(const float4*)(xbase + (size_t)i * 4 * IN_DIM
                                                       + (size_t)(jj + 2) * BK);
                }
            } else {
                // prefetch next x chunk (consumed by cvt at chunk end)
                if (jj + 1 < NITER) {
                    #pragma unroll
                    for (int i = 0; i < 8; i++)
                        xr[i] = *(const float4*)(xbase + (size_t)i * 4 * IN_DIM
                                                       + (size_t)(jj + 1) * BK);
                }
            }

            // ---- compute chunk jj: 2 k16 steps, 2 fp32 GEMMs ----
            #pragma unroll
            for (int kk = 0; kk < 2; kk++) {
                const uint32_t ko = (uint32_t)kk * 32;
                // --- GEMM 1: main = h1*w1 ---
                {
                    uint32_t w1f[4][4], aH[2][4];
                    #pragma unroll
                    for (int gg = 0; gg < 4; gg++)
                        ldsm4(w1f[gg], sb + bchunk + b_ld + (uint32_t)gg * 1280 + ko);
                    ldsm4(aH[0], sb + astage + a_ld + ko);
                    ldsm4(aH[1], sb + astage + a_ld + 1280 + ko);
                    #pragma unroll
                    for (int gg = 0; gg < 4; gg++)
                        #pragma unroll
                        for (int m = 0; m < 2; m++) {
                            mma_f32(&accM[m][(2 * gg) * 4],     aH[m], w1f[gg][0], w1f[gg][1]);
                            mma_f32(&accM[m][(2 * gg + 1) * 4], aH[m], w1f[gg][2], w1f[gg][3]);
                        }
                }
                // --- GEMM 2: ST = S*T ---
                {
                    uint32_t tf[4][4], aS[2][4];
                    #pragma unroll
                    for (int gg = 0; gg < 4; gg++)
                        ldsm4(tf[gg], sb + bchunk + B_OFF_T + b_ld + (uint32_t)gg * 1280 + ko);
                    ldsm4(aS[0], sb + astage + A_OFF_S + a_ld + ko);
                    ldsm4(aS[1], sb + astage + A_OFF_S + a_ld + 1280 + ko);
                    #pragma unroll
                    for (int gg = 0; gg < 4; gg++)
                        #pragma unroll
                        for (int m = 0; m < 2; m++) {
                            mma_f32(&accS[m][(2 * gg) * 4],     aS[m], tf[gg][0], tf[gg][1]);
                            mma_f32(&accS[m][(2 * gg + 1) * 4], aS[m], tf[gg][2], tf[gg][3]);
                        }
                }
            }

            if (!cvtFirst) {
                // stage next A chunk (warp-private)
                if (jj + 1 < NITER) {
                    char* Ab = smch + (size_t)((jj + 1) & 1) * A_STAGE_B;
                    #pragma unroll
                    for (int i = 0; i < 8; i++)
                        cvt_store(Ab, st_base + (uint32_t)i * 320, xr[i]);
                }
            }
            __syncwarp();
        }

        CP_WAIT0();
        __syncthreads();
    }

    // ================= epilogue =================
    const int q  = lane >> 2;   // row-in-8
    const int qc = lane & 3;    // column quad slot
    float* outIdx = out;
    float* outW   = out + 2 * (size_t)N_TOKENS;
    float* probs  = out + 4 * (size_t)N_TOKENS;

    #pragma unroll
    for (int m = 0; m < 2; m++) {
        #pragma unroll
        for (int r = 0; r < 2; r++) {
            // logit = main + (ST - main)/BETA
            float v[16];
            #pragma unroll
            for (int f = 0; f < 8; f++) {
                float m0 = accM[m][f * 4 + 2 * r],     s0 = accS[m][f * 4 + 2 * r];
                float m1 = accM[m][f * 4 + 2 * r + 1], s1 = accS[m][f * 4 + 2 * r + 1];
                v[2 * f]     = fmaf(s0 - m0, INV_BETA, m0);
                v[2 * f + 1] = fmaf(s1 - m1, INV_BETA, m1);
            }
            // quad max
            float mx = v[0];
            #pragma unroll
            for (int i = 1; i < 16; i++) mx = fmaxf(mx, v[i]);
            mx = fmaxf(mx, __shfl_xor_sync(0xffffffffu, mx, 1));
            mx = fmaxf(mx, __shfl_xor_sync(0xffffffffu, mx, 2));

            // local top-2 on logits (e ascending within lane)
            float v1 = -3.4e38f, v2 = -3.4e38f;
            int   i1 = 0, i2 = 0;
            #pragma unroll
            for (int f = 0; f < 8; f++) {
                #pragma unroll
                for (int cch = 0; cch < 2; cch++) {
                    float val = v[2 * f + cch];
                    int   e   = f * 8 + qc * 2 + cch;
                    if (val > v1)      { v2 = v1; i2 = i1; v1 = val; i1 = e; }
                    else if (val > v2) { v2 = val; i2 = e; }
                }
            }
            // quad merge (tie -> lower index, matching jax)
            #pragma unroll
            for (int d = 1; d <= 2; d <<= 1) {
                float ov1 = __shfl_xor_sync(0xffffffffu, v1, d);
                int   oi1 = __shfl_xor_sync(0xffffffffu, i1, d);
                float ov2 = __shfl_xor_sync(0xffffffffu, v2, d);
                int   oi2 = __shfl_xor_sync(0xffffffffu, i2, d);
                bool bet1 = (ov1 > v1) || (ov1 == v1 && oi1 < i1);
                if (bet1) {
                    bool keepOld = (v1 > ov2) || (v1 == ov2 && i1 < oi2);
                    if (keepOld) { v2 = v1; i2 = i1; } else { v2 = ov2; i2 = oi2; }
                    v1 = ov1; i1 = oi1;
                } else {
                    bool bet2 = (ov1 > v2) || (ov1 == v2 && oi1 < i2);
                    if (bet2) { v2 = ov1; i2 = oi1; }
                }
            }

            // exp + quad sum
            float ssum = 0.0f;
            #pragma unroll
            for (int i = 0; i < 16; i++) { v[i] = __expf(v[i] - mx); ssum += v[i]; }
            ssum += __shfl_xor_sync(0xffffffffu, ssum, 1);
            ssum += __shfl_xor_sync(0xffffffffu, ssum, 2);
            float rinv = 1.0f / ssum;

            const int row = tokenBase + w * 32 + m * 16 + q + r * 8;
            float* pr = probs + (size_t)row * N_EXPERTS + qc * 2;
            #pragma unroll
            for (int f = 0; f < 8; f++) {
                float2 pv = make_float2(v[2 * f] * rinv, v[2 * f + 1] * rinv);
                *(float2*)(pr + f * 8) = pv;
            }
            if (qc == 0) {
                float p1 = __expf(v1 - mx), p2 = __expf(v2 - mx);
                outIdx[(size_t)row * 2 + 0] = (float)i1;
                outIdx[(size_t)row * 2 + 1] = (float)i2;
                float tw = 1.0f / (p1 + p2);
                outW[(size_t)row * 2 + 0] = p1 * tw;
                outW[(size_t)row * 2 + 1] = p2 * tw;
            }
        }
    }
}

// ---------------------------------------------------------------- launcher
extern "C" void kernel_launch(void* const* d_in, const int* in_sizes, int n_in,
                              void* d_out, int out_size) {
    const float* x = (const float*)d_in[0];   // [65536, 2048] fp32
    const float* W = (const float*)d_in[1];   // [64, 2048]   fp32
    float* out = (float*)d_out;

    static int configured = 0;
    if (!configured) {
        cudaFuncSetAttribute(router_mma_kernel,
                             cudaFuncAttributeMaxDynamicSharedMemorySize, SMEM_BYTES);
        configured = 1;
    }

    wsplit_kernel<<<(N_EXPERTS * IN_DIM) / 256, 256>>>(W);
    router_mma_kernel<<<GRID_CTAS, NTHREADS, SMEM_BYTES>>>(x, out);
}